// round 16
// baseline (speedup 1.0000x reference)
#include <cuda_runtime.h>
#include <cuda_bf16.h>
#include <cstdint>

#define N_ROIS   32768
#define N_GT     1024
#define N_IMAGES 8
#define NT       512
#define NB       148                 // 1 block per SM, single wave
#define NGT_PAD  1152
#define MAXROI   224                 // >= max nroi (222)

// shared-GT dual-ROI step: one LDS feeds both ROIs of the pair
#define IOU2_STEP(J, BA, JA, BP, JP) {                          \
    float4 g  = sbox[J];                                        \
    float ag  = sarea[J];                                       \
    /* ROI A */                                                 \
    float iwa = fminf(ax2p, g.z) - fmaxf(ax1, g.x);             \
    float iha = fminf(ay2p, g.w) - fmaxf(ay1, g.y);             \
    float ina = fmaxf(iwa, 0.0f) * iha;                         \
    float una = (area_a + ag) - ina;                            \
    float iva = __fdividef(ina, una);                           \
    bool ba_ = iva > (BA);                                      \
    BA = ba_ ? iva : (BA);                                      \
    JA = ba_ ? (J) : (JA);                                      \
    /* ROI B */                                                 \
    float iwb = fminf(bx2p, g.z) - fmaxf(bx1, g.x);             \
    float ihb = fminf(by2p, g.w) - fmaxf(by1, g.y);             \
    float inb = fmaxf(iwb, 0.0f) * ihb;                         \
    float unb = (area_b + ag) - inb;                            \
    float ivb = __fdividef(inb, unb);                           \
    bool bb_ = ivb > (BP);                                      \
    BP = bb_ ? ivb : (BP);                                      \
    JP = bb_ ? (J) : (JP);                                      \
}

#define MERGEV(BST, BJ, OB, OJ) {                               \
    bool take = ((OB) > (BST)) ||                               \
        ((OB) == (BST) && (unsigned)(OJ) < (unsigned)(BJ));     \
    BST = take ? (OB) : (BST);                                  \
    BJ  = take ? (OJ) : (BJ);                                   \
}

__global__ void __launch_bounds__(NT, 1) roitarget_fused(const float* __restrict__ rois,
                                                         const int* __restrict__ rb,
                                                         const float* __restrict__ gt,
                                                         const int* __restrict__ gb,
                                                         float* __restrict__ out) {
    __shared__ float  sgt[5 * N_GT];       // 20KB raw staged gt (coalesced)
    __shared__ float4 sbox[NGT_PAD];       // 18.4KB compacted boxes (+pads)
    __shared__ float  sarea[NGT_PAD];      // 4.6KB areas (+pads)
    __shared__ float  slab[NGT_PAD];       // 4.6KB labels
    __shared__ float4 sroi[MAXROI];        // 3.5KB ROI coords by local index
    __shared__ int    sgcnt[32][9];        // per-chunk per-batch GT counts (zeroed)
    __shared__ int    sexcl[32][9];        // exclusive chunk prefix
    __shared__ int    stot[N_IMAGES];
    __shared__ int    soff[N_IMAGES + 1];  // padded GT batch offsets
    __shared__ int    snf[N_IMAGES];       // padded len / 16
    __shared__ int    swc[7][8];           // ROI counts per warp/batch (zeroed)
    __shared__ int    wbase[7][8];
    __shared__ int    rstart[N_IMAGES + 1];// ROI bucket starts
    __shared__ int    pairoff[N_IMAGES + 1];// pair-slot offsets
    __shared__ int    ssrc[MAXROI];        // sorted pos -> local ROI index

    const int tid  = threadIdx.x;
    const int w    = tid >> 5;
    const int lane = tid & 31;
    const unsigned lt = (1u << lane) - 1u;

    const int start = (blockIdx.x * N_ROIS) / NB;
    const int next  = ((blockIdx.x + 1) * N_ROIS) / NB;
    const int nroi  = next - start;        // 221 or 222

    // ---- zero count matrices (before any counting) ----
    if (tid < 288) (&sgcnt[0][0])[tid] = 0;
    else if (tid < 288 + 56) (&swc[0][0])[tid - 288] = 0;

    // ---- coalesced GT staging + hoisted loads ----
#pragma unroll
    for (int k = 0; k < 10; k++) sgt[tid + k * NT] = gt[tid + k * NT];
    const int ja = tid, jb = tid + NT;     // chunks w and 16+w
    const int ba  = gb[ja];
    const int bb2 = gb[jb];
    int myb = -1;
    if (tid < nroi) {
        const int i = start + tid;
        myb = rb[i];
        sroi[tid] = make_float4(rois[5*i+0], rois[5*i+1], rois[5*i+2], rois[5*i+3]);
    }
    __syncthreads();                       // sync 0 (zeroing visible)

    // ---- match_any counting: GT chunks (all warps, 2 chunks each) ----
    const unsigned ma = __match_any_sync(0xffffffffu, ba);
    const int ranka = __popc(ma & lt);
    if (!(ma & lt)) sgcnt[w][ba] = __popc(ma);
    const unsigned mb = __match_any_sync(0xffffffffu, bb2);
    const int rankb = __popc(mb & lt);
    if (!(mb & lt)) sgcnt[16 + w][bb2] = __popc(mb);

    // ---- match_any counting: ROIs (warps 0-6; invalid lanes carry -1) ----
    int rank = 0;
    if (w < 7) {
        unsigned mr = __match_any_sync(0xffffffffu, myb);
        rank = __popc(mr & lt);
        if (myb >= 0 && !(mr & lt)) swc[w][myb] = __popc(mr);
    }
    __syncthreads();                       // sync 1

    // ---- scans: warps 0-7 GT chunk-scan; warps 8-9 ROI bases (serial) ----
    if (w < N_IMAGES) {
        int v = sgcnt[lane][w];
        int incl = v;
#pragma unroll
        for (int d = 1; d < 32; d <<= 1) {
            int t = __shfl_up_sync(0xffffffffu, incl, d);
            if (lane >= d) incl += t;
        }
        sexcl[lane][w] = incl - v;
        if (lane == 31) stot[w] = incl;
    } else if (w == 8 || w == 9) {
        int e = (w - 8) * 32 + lane;       // 0..63
        if (e < 56) {
            int ww = e % 7, b2 = e / 7;
            int o = 0;
            for (int b3 = 0; b3 < b2; b3++)
#pragma unroll
                for (int w2 = 0; w2 < 7; w2++) o += swc[w2][b3];
            for (int w2 = 0; w2 < ww; w2++) o += swc[w2][b2];
            wbase[ww][b2] = o;
        }
    }
    __syncthreads();                       // sync 2

    // ---- per-warp redundant offsets (identical values; no barrier) ----
    if (lane == 0) {
        int o = 0;
#pragma unroll
        for (int b = 0; b < N_IMAGES; b++) {
            int plen = (stot[b] + 15) & ~15;
            soff[b] = o; snf[b] = plen >> 4; o += plen;
        }
        soff[N_IMAGES] = o;
#pragma unroll
        for (int b = 0; b < N_IMAGES; b++) rstart[b] = wbase[0][b];
        rstart[N_IMAGES] = nroi;
        int po = 0;
#pragma unroll
        for (int b = 0; b < N_IMAGES; b++) {
            int nb2 = (b < 7 ? wbase[0][b + 1] : nroi) - wbase[0][b];
            pairoff[b] = po;
            po += (nb2 + 1) >> 1;
        }
        pairoff[N_IMAGES] = po;
    }
    __syncwarp();

    // ---- GT parse + scatter ----
    {
        const float x1 = sgt[5*ja+0], y1 = sgt[5*ja+1];
        const float x2 = sgt[5*ja+2], y2 = sgt[5*ja+3], cls = sgt[5*ja+4];
        const int da = soff[ba] + sexcl[w][ba] + ranka;
        sbox[da]  = make_float4(x1, y1, x2 + 1.0f, y2 + 1.0f);
        sarea[da] = ((x2 - x1) + 1.0f) * ((y2 - y1) + 1.0f);
        slab[da]  = cls;

        const float u1 = sgt[5*jb+0], v1 = sgt[5*jb+1];
        const float u2 = sgt[5*jb+2], v2 = sgt[5*jb+3], cl2 = sgt[5*jb+4];
        const int db = soff[bb2] + sexcl[16 + w][bb2] + rankb;
        sbox[db]  = make_float4(u1, v1, u2 + 1.0f, v2 + 1.0f);
        sarea[db] = ((u2 - u1) + 1.0f) * ((v2 - v1) + 1.0f);
        slab[db]  = cl2;
    }
    // ---- pad entries (never win: inter == 0, uni > 0) ----
    if (tid < 128) {
        const int b = tid >> 4, k = tid & 15;
        const int cnt  = stot[b];
        const int plen = (cnt + 15) & ~15;
        if (k < plen - cnt) {
            const int slot = soff[b] + cnt + k;
            sbox[slot]  = make_float4(3e9f, 0.0f, 1e9f, 1e9f);
            sarea[slot] = 1.0f;
            slab[slot]  = 0.0f;
        }
    }
    // ---- ROI scatter (rank/myb kept in registers across barriers) ----
    if (myb >= 0) {
        int dest = wbase[w][myb] + rank;
        ssrc[dest] = tid;
    }
    __syncthreads();                       // sync 3

    // ---------------- Phase 3: thread-quad per ROI PAIR --------------------
    const int s = tid >> 2;                // pair slot 0..127
    const int q = tid & 3;                 // quarter
    const int npairs = pairoff[N_IMAGES];
    const bool valid = (s < npairs);

    int b = 0;
#pragma unroll
    for (int k = 1; k < N_IMAGES; k++) b += (s >= pairoff[k]);
    const int k2   = s - pairoff[b];
    const int rcnt = rstart[b + 1] - rstart[b];
    const int pa   = valid ? (rstart[b] + 2 * k2) : 0;
    const bool dual = valid && (2 * k2 + 1 < rcnt);
    const int pbx  = pa + (dual ? 1 : 0);
    const int loca = ssrc[pa];
    const int locb = ssrc[pbx];

    const float4 ra = sroi[loca];
    const float ax1 = ra.x, ay1 = ra.y;
    const float ax2p = ra.z + 1.0f, ay2p = ra.w + 1.0f;
    const float aew = (ra.z - ax1) + 1.0f, aeh = (ra.w - ay1) + 1.0f;
    const float area_a = aew * aeh;

    const float4 rbv = sroi[locb];
    const float bx1 = rbv.x, by1 = rbv.y;
    const float bx2p = rbv.z + 1.0f, by2p = rbv.w + 1.0f;
    const float bew = (rbv.z - bx1) + 1.0f, beh = (rbv.w - by1) + 1.0f;
    const float area_b = bew * beh;

    const int j0 = soff[b];
    const int nfull = valid ? snf[b] : 0;

    float ba0 = 0.0f; int ja0 = -1;        // ROI A chains
    float ba1 = 0.0f; int ja1 = -1;
    float bp0 = 0.0f; int jp0 = -1;        // ROI B chains
    float bp1 = 0.0f; int jp1 = -1;

    int base = j0 + q;
    for (int t = 0; t < nfull; t++, base += 16) {
        IOU2_STEP(base + 0,  ba0, ja0, bp0, jp0);
        IOU2_STEP(base + 4,  ba1, ja1, bp1, jp1);
        IOU2_STEP(base + 8,  ba0, ja0, bp0, jp0);
        IOU2_STEP(base + 12, ba1, ja1, bp1, jp1);
    }

    // in-thread chain merges (ties -> smaller j)
    float bestA = ba0; int bjA = ja0;
    MERGEV(bestA, bjA, ba1, ja1);
    float bestB = bp0; int bjB = jp0;
    MERGEV(bestB, bjB, bp1, jp1);

    // cross-quarter butterfly merges (all lanes participate)
#pragma unroll
    for (int d = 1; d <= 2; d <<= 1) {
        float oa = __shfl_xor_sync(0xffffffffu, bestA, d);
        int   na = __shfl_xor_sync(0xffffffffu, bjA, d);
        MERGEV(bestA, bjA, oa, na);
        float ob = __shfl_xor_sync(0xffffffffu, bestB, d);
        int   nb2 = __shfl_xor_sync(0xffffffffu, bjB, d);
        MERGEV(bestB, bjB, ob, nb2);
    }

    // epilogue: q==0 stores ROI A; q==1 stores ROI B (if distinct)
    if (valid && (q == 0 || (q == 1 && dual))) {
        const bool isA = (q == 0);
        const float best = isA ? bestA : bestB;
        const int   bj   = isA ? bjA   : bjB;
        const int   loc  = isA ? loca  : locb;
        const float rx1v = isA ? ax1 : bx1;
        const float ry1v = isA ? ay1 : by1;
        const float ewv  = isA ? aew : bew;
        const float ehv  = isA ? aeh : beh;

        const bool fg = (bj >= 0) && (best >= 0.5f);
        const int ii = start + loc;

        float lbl = 0.0f, dx = 0.0f, dy = 0.0f, dw = 0.0f, dh = 0.0f, wgt = 0.0f;
        if (fg) {
            float4 g = sbox[bj];
            float gw  = g.z - g.x;             // (x2+1) - x1
            float gh  = g.w - g.y;
            float gcx = g.x + 0.5f * gw;
            float gcy = g.y + 0.5f * gh;
            float ecx = rx1v + 0.5f * ewv;
            float ecy = ry1v + 0.5f * ehv;
            dx = __fdividef(gcx - ecx, ewv);
            dy = __fdividef(gcy - ecy, ehv);
            dw = __logf(__fdividef(gw, ewv));
            dh = __logf(__fdividef(gh, ehv));
            lbl = slab[bj];
            wgt = 1.0f;
        }

        // Layout: labels[N] | deltas[N][4] | bbwgts[N][1]
        out[ii] = lbl;
        reinterpret_cast<float4*>(out + N_ROIS)[ii] = make_float4(dx, dy, dw, dh);
        out[N_ROIS * 5 + ii] = wgt;
    }
}

extern "C" void kernel_launch(void* const* d_in, const int* in_sizes, int n_in,
                              void* d_out, int out_size) {
    const float* rois = (const float*)d_in[0];
    const int*   rb   = (const int*)d_in[1];
    const float* gt   = (const float*)d_in[2];
    const int*   gb   = (const int*)d_in[3];
    float* out = (float*)d_out;

    roitarget_fused<<<NB, NT>>>(rois, rb, gt, gb, out);
}